// round 1
// baseline (speedup 1.0000x reference)
#include <cuda_runtime.h>

#define B  32
#define CI 64
#define CO 128
#define KK 3
#define LL 8192
#define TL 256

// Scratch (allocation-free rule: __device__ globals)
__device__ float g_S[B * CI];
__device__ float g_win[B * CI * KK];
__device__ float g_wout[B * CO];
__device__ float g_bias[B * CO];

// ---------------------------------------------------------------------------
// Kernel 1: per-(b,c) row sums of x.  2048 blocks x 256 threads, float4 loads.
// ---------------------------------------------------------------------------
__global__ void rowsum_kernel(const float* __restrict__ x) {
    int row = blockIdx.x;
    const float4* p = reinterpret_cast<const float4*>(x + (size_t)row * LL);
    float s = 0.f;
#pragma unroll
    for (int i = threadIdx.x; i < LL / 4; i += 256) {
        float4 v = p[i];
        s += v.x + v.y + v.z + v.w;
    }
    __shared__ float red[256];
    red[threadIdx.x] = s;
    __syncthreads();
    for (int st = 128; st > 0; st >>= 1) {
        if (threadIdx.x < st) red[threadIdx.x] += red[threadIdx.x + st];
        __syncthreads();
    }
    if (threadIdx.x == 0) g_S[row] = red[0];
}

// ---------------------------------------------------------------------------
// Kernel 2: per-batch "maker" math.  32 blocks x 192 threads.
// kern[b,c,j] = (Wk[c3j,0]*(S - x_last) + Wk[c3j,1]*S + Wk[c3j,2]*(S - x_0)) / L
// w_in[b,o,k] = sum_c kern[b,c,k] * W_in[o,c]
// w_out[b,o]  = sum_{c,k} kern[b,c,k] * W_out[o,c,k]
// bias[b,o]   = sum_{c,k} kern[b,c,k] * W_bias[o,c,k]
// ---------------------------------------------------------------------------
__global__ void maker_kernel(const float* __restrict__ x,
                             const float* __restrict__ Wk,
                             const float* __restrict__ Win,
                             const float* __restrict__ Wout,
                             const float* __restrict__ Wbias) {
    int b = blockIdx.x;
    int tid = threadIdx.x;
    __shared__ float kern[CI * KK];
    __shared__ float sS[CI], sx0[CI], sxl[CI];

    if (tid < CI) {
        sS[tid] = g_S[b * CI + tid];
        const float* xb = x + ((size_t)b * CI + tid) * LL;
        sx0[tid] = xb[0];
        sxl[tid] = xb[LL - 1];
    }
    __syncthreads();

    if (tid < CI * KK) {
        int c = tid / KK;
        float S = sS[c];
        float t0 = S - sxl[c];
        float t2 = S - sx0[c];
        kern[tid] = (Wk[tid * 3 + 0] * t0 + Wk[tid * 3 + 1] * S +
                     Wk[tid * 3 + 2] * t2) * (1.0f / LL);
    }
    __syncthreads();

    if (tid < CI * KK) {
        int o = tid / KK, k = tid % KK;
        float acc = 0.f;
#pragma unroll 8
        for (int c = 0; c < CI; c++) acc += kern[c * KK + k] * Win[o * CI + c];
        g_win[b * CI * KK + tid] = acc;
    }
    if (tid < CO) {
        float wo = 0.f, bi = 0.f;
#pragma unroll 4
        for (int i = 0; i < CI * KK; i++) {
            float kv = kern[i];
            wo += kv * Wout[tid * CI * KK + i];
            bi += kv * Wbias[tid * CI * KK + i];
        }
        g_wout[b * CO + tid] = wo;
        g_bias[b * CO + tid] = bi;
    }
}

// ---------------------------------------------------------------------------
// Kernel 3: z[b,l] = sum_{c,k} x_pad[b,c,l+k-1]*w_in[b,c,k];
//           y[b,o,l] = w_out[b,o]*z + bias[b,o].
// Grid (L/TL, B), 256 threads.  x tile (64 x 258) staged in dynamic smem,
// vectorized float4 stores for the 128-channel broadcast epilogue.
// ---------------------------------------------------------------------------
__global__ void out_kernel(const float* __restrict__ x, float* __restrict__ y) {
    extern __shared__ float sm[];
    float* sx    = sm;                         // CI*(TL+2)
    float* swin  = sx + CI * (TL + 2);         // CI*KK
    float* swout = swin + CI * KK;             // CO
    float* sbias = swout + CO;                 // CO
    float* sz    = sbias + CO;                 // TL

    int b = blockIdx.y;
    int lbase = blockIdx.x * TL;
    int tid = threadIdx.x;

    if (tid < CI * KK) swin[tid] = g_win[b * CI * KK + tid];
    if (tid < CO) {
        swout[tid] = g_wout[b * CO + tid];
        sbias[tid] = g_bias[b * CO + tid];
    }

    const float* xb = x + (size_t)b * CI * LL;
    for (int idx = tid; idx < CI * (TL + 2); idx += TL) {
        int c = idx / (TL + 2);
        int off = idx - c * (TL + 2);
        int gl = lbase + off - 1;
        sx[idx] = (gl >= 0 && gl < LL) ? xb[c * LL + gl] : 0.f;
    }
    __syncthreads();

    float z = 0.f;
#pragma unroll
    for (int c = 0; c < CI; c++) {
        const float* row = sx + c * (TL + 2) + tid;
        z += swin[c * 3 + 0] * row[0] + swin[c * 3 + 1] * row[1] +
             swin[c * 3 + 2] * row[2];
    }
    sz[tid] = z;
    __syncthreads();

    float4* y4 = reinterpret_cast<float4*>(y + (size_t)b * CO * LL + lbase);
    const float4* sz4 = reinterpret_cast<const float4*>(sz);
    for (int i = tid; i < CO * (TL / 4); i += TL) {
        int o = i / (TL / 4);
        int l4 = i - o * (TL / 4);
        float4 zv = sz4[l4];
        float wo = swout[o], bi = sbias[o];
        float4 r;
        r.x = __fmaf_rn(wo, zv.x, bi);
        r.y = __fmaf_rn(wo, zv.y, bi);
        r.z = __fmaf_rn(wo, zv.z, bi);
        r.w = __fmaf_rn(wo, zv.w, bi);
        y4[(size_t)o * (LL / 4) + l4] = r;
    }
}

// ---------------------------------------------------------------------------
extern "C" void kernel_launch(void* const* d_in, const int* in_sizes, int n_in,
                              void* d_out, int out_size) {
    const float* x     = (const float*)d_in[0];
    const float* Wk    = (const float*)d_in[1];
    const float* Win   = (const float*)d_in[2];
    const float* Wout  = (const float*)d_in[3];
    const float* Wbias = (const float*)d_in[4];
    float* y = (float*)d_out;

    const size_t smem =
        (CI * (TL + 2) + CI * KK + CO + CO + TL) * sizeof(float);
    cudaFuncSetAttribute(out_kernel,
                         cudaFuncAttributeMaxDynamicSharedMemorySize,
                         (int)smem);

    rowsum_kernel<<<B * CI, 256>>>(x);
    maker_kernel<<<B, 192>>>(x, Wk, Win, Wout, Wbias);
    dim3 grid(LL / TL, B);
    out_kernel<<<grid, TL, smem>>>(x, y);
}

// round 3
// speedup vs baseline: 1.0402x; 1.0402x over previous
#include <cuda_runtime.h>

#define B  32
#define CI 64
#define CO 128
#define KK 3
#define LL 8192
#define TL 512          // l-positions per block in out_kernel
#define OTH 128         // threads in out_kernel (4 l per thread)

__device__ float g_S[B * CI];
__device__ float g_win[B * CI * KK];
__device__ float g_wout[B * CO];
__device__ float g_bias[B * CO];

// ---------------------------------------------------------------------------
// Kernel 1: per-(b,c) row sums. 2048 blocks x 256 threads.
// 8 independent float4 loads (MLP=8), warp-shuffle reduce, 1 barrier.
// ---------------------------------------------------------------------------
__global__ __launch_bounds__(256) void rowsum_kernel(const float* __restrict__ x) {
    const int row = blockIdx.x;
    const float4* p = reinterpret_cast<const float4*>(x + (size_t)row * LL);

    float4 v[8];
#pragma unroll
    for (int j = 0; j < 8; j++) v[j] = p[threadIdx.x + j * 256];

    float s = 0.f;
#pragma unroll
    for (int j = 0; j < 8; j++) s += (v[j].x + v[j].y) + (v[j].z + v[j].w);

#pragma unroll
    for (int off = 16; off > 0; off >>= 1)
        s += __shfl_xor_sync(0xffffffffu, s, off);

    __shared__ float wsum[8];
    if ((threadIdx.x & 31) == 0) wsum[threadIdx.x >> 5] = s;
    __syncthreads();
    if (threadIdx.x == 0) {
        float t = 0.f;
#pragma unroll
        for (int w = 0; w < 8; w++) t += wsum[w];
        g_S[row] = t;
    }
}

// ---------------------------------------------------------------------------
// Kernel 2: per-batch maker math. 32 blocks x 192 threads.
// kern[b,c,j] = (Wk[c3j,0]*(S-x_last) + Wk[c3j,1]*S + Wk[c3j,2]*(S-x_0)) / L
// ---------------------------------------------------------------------------
__global__ void maker_kernel(const float* __restrict__ x,
                             const float* __restrict__ Wk,
                             const float* __restrict__ Win,
                             const float* __restrict__ Wout,
                             const float* __restrict__ Wbias) {
    int b = blockIdx.x;
    int tid = threadIdx.x;
    __shared__ float kern[CI * KK];
    __shared__ float sS[CI], sx0[CI], sxl[CI];

    if (tid < CI) {
        sS[tid] = g_S[b * CI + tid];
        const float* xb = x + ((size_t)b * CI + tid) * LL;
        sx0[tid] = xb[0];
        sxl[tid] = xb[LL - 1];
    }
    __syncthreads();

    if (tid < CI * KK) {
        int c = tid / KK;
        float S = sS[c];
        float t0 = S - sxl[c];
        float t2 = S - sx0[c];
        kern[tid] = (Wk[tid * 3 + 0] * t0 + Wk[tid * 3 + 1] * S +
                     Wk[tid * 3 + 2] * t2) * (1.0f / LL);
    }
    __syncthreads();

    if (tid < CI * KK) {
        int o = tid / KK, k = tid % KK;
        float acc = 0.f;
#pragma unroll 8
        for (int c = 0; c < CI; c++) acc += kern[c * KK + k] * Win[o * CI + c];
        g_win[b * CI * KK + tid] = acc;
    }
    if (tid < CO) {
        float wo = 0.f, bi = 0.f;
#pragma unroll 4
        for (int i = 0; i < CI * KK; i++) {
            float kv = kern[i];
            wo += kv * Wout[tid * CI * KK + i];
            bi += kv * Wbias[tid * CI * KK + i];
        }
        g_wout[b * CO + tid] = wo;
        g_bias[b * CO + tid] = bi;
    }
}

// ---------------------------------------------------------------------------
// Kernel 3: register-resident z + broadcast epilogue (no smem x staging).
// Each thread owns 4 consecutive l. Halo via warp shuffle; warp-edge lanes
// fetch the 2 boundary scalars from global (L1/L2 hit).
// Grid (LL/TL, B) = (16, 32), 128 threads. smem = 1.8KB (weights only).
// ---------------------------------------------------------------------------
__global__ __launch_bounds__(OTH) void out_kernel(const float* __restrict__ x,
                                                  float* __restrict__ y) {
    __shared__ float swin[CI * KK];
    __shared__ float swout[CO];
    __shared__ float sbias[CO];

    const int b = blockIdx.y;
    const int lbase = blockIdx.x * TL;
    const int tid = threadIdx.x;
    const int lane = tid & 31;
    const int l0 = lbase + tid * 4;

    if (tid < CO) {
        swout[tid] = g_wout[b * CO + tid];
        sbias[tid] = g_bias[b * CO + tid];
    }
    for (int i = tid; i < CI * KK; i += OTH)
        swin[i] = g_win[b * CI * KK + i];
    __syncthreads();

    const float* xb = x + (size_t)b * CI * LL;

    float zx = 0.f, zy = 0.f, zz = 0.f, zw = 0.f;

#pragma unroll 8
    for (int c = 0; c < CI; c++) {
        const float* xc = xb + (size_t)c * LL;
        float4 v = *reinterpret_cast<const float4*>(xc + l0);

        float lm = __shfl_up_sync(0xffffffffu, v.w, 1);
        if (lane == 0) lm = (l0 > 0) ? xc[l0 - 1] : 0.f;
        float rp = __shfl_down_sync(0xffffffffu, v.x, 1);
        if (lane == 31) rp = (l0 + 4 < LL) ? xc[l0 + 4] : 0.f;

        float w0 = swin[c * 3 + 0];
        float w1 = swin[c * 3 + 1];
        float w2 = swin[c * 3 + 2];

        zx = __fmaf_rn(w0, lm,  __fmaf_rn(w1, v.x, __fmaf_rn(w2, v.y, zx)));
        zy = __fmaf_rn(w0, v.x, __fmaf_rn(w1, v.y, __fmaf_rn(w2, v.z, zy)));
        zz = __fmaf_rn(w0, v.y, __fmaf_rn(w1, v.z, __fmaf_rn(w2, v.w, zz)));
        zw = __fmaf_rn(w0, v.z, __fmaf_rn(w1, v.w, __fmaf_rn(w2, rp,  zw)));
    }

    // Broadcast epilogue straight from registers: y[b,o,l0..l0+3]
    float* yb = y + (size_t)b * CO * LL + l0;
#pragma unroll 4
    for (int o = 0; o < CO; o++) {
        float wo = swout[o], bi = sbias[o];
        float4 r;
        r.x = __fmaf_rn(wo, zx, bi);
        r.y = __fmaf_rn(wo, zy, bi);
        r.z = __fmaf_rn(wo, zz, bi);
        r.w = __fmaf_rn(wo, zw, bi);
        *reinterpret_cast<float4*>(yb + (size_t)o * LL) = r;
    }
}

// ---------------------------------------------------------------------------
extern "C" void kernel_launch(void* const* d_in, const int* in_sizes, int n_in,
                              void* d_out, int out_size) {
    const float* x     = (const float*)d_in[0];
    const float* Wk    = (const float*)d_in[1];
    const float* Win   = (const float*)d_in[2];
    const float* Wout  = (const float*)d_in[3];
    const float* Wbias = (const float*)d_in[4];
    float* y = (float*)d_out;

    rowsum_kernel<<<B * CI, 256>>>(x);
    maker_kernel<<<B, 192>>>(x, Wk, Win, Wout, Wbias);
    dim3 grid(LL / TL, B);
    out_kernel<<<grid, OTH>>>(x, y);
}

// round 4
// speedup vs baseline: 1.2056x; 1.1590x over previous
#include <cuda_runtime.h>

#define B   32
#define CI  64
#define CO  128
#define KK  3
#define LL  8192

#define ZTH 256
#define ZTL (ZTH * 4)    // 1024 l per z-block
#define CG  4            // c-groups
#define CPG (CI / CG)    // 16 channels per group

#define YTH 256
#define YTL 512          // l per y-block

__device__ float g_S[B * CI];
__device__ float g_win[B * CI * KK];
__device__ float g_wout[B * CO];
__device__ float g_bias[B * CO];
__device__ float g_zp[CG][B][LL];   // 4MB z partials

// ---------------------------------------------------------------------------
// Kernel 1: per-(b,c) row sums. 2048 blocks x 256 threads.
// ---------------------------------------------------------------------------
__global__ __launch_bounds__(256) void rowsum_kernel(const float* __restrict__ x) {
    const int row = blockIdx.x;
    const float4* p = reinterpret_cast<const float4*>(x + (size_t)row * LL);

    float4 v[8];
#pragma unroll
    for (int j = 0; j < 8; j++) v[j] = p[threadIdx.x + j * 256];

    float s = 0.f;
#pragma unroll
    for (int j = 0; j < 8; j++) s += (v[j].x + v[j].y) + (v[j].z + v[j].w);

#pragma unroll
    for (int off = 16; off > 0; off >>= 1)
        s += __shfl_xor_sync(0xffffffffu, s, off);

    __shared__ float wsum[8];
    if ((threadIdx.x & 31) == 0) wsum[threadIdx.x >> 5] = s;
    __syncthreads();
    if (threadIdx.x == 0) {
        float t = 0.f;
#pragma unroll
        for (int w = 0; w < 8; w++) t += wsum[w];
        g_S[row] = t;
    }
}

// ---------------------------------------------------------------------------
// Kernel 2: per-batch maker math. 32 blocks x 192 threads.
// ---------------------------------------------------------------------------
__global__ void maker_kernel(const float* __restrict__ x,
                             const float* __restrict__ Wk,
                             const float* __restrict__ Win,
                             const float* __restrict__ Wout,
                             const float* __restrict__ Wbias) {
    int b = blockIdx.x;
    int tid = threadIdx.x;
    __shared__ float kern[CI * KK];
    __shared__ float sS[CI], sx0[CI], sxl[CI];

    if (tid < CI) {
        sS[tid] = g_S[b * CI + tid];
        const float* xb = x + ((size_t)b * CI + tid) * LL;
        sx0[tid] = xb[0];
        sxl[tid] = xb[LL - 1];
    }
    __syncthreads();

    if (tid < CI * KK) {
        int c = tid / KK;
        float S = sS[c];
        float t0 = S - sxl[c];
        float t2 = S - sx0[c];
        kern[tid] = (Wk[tid * 3 + 0] * t0 + Wk[tid * 3 + 1] * S +
                     Wk[tid * 3 + 2] * t2) * (1.0f / LL);
    }
    __syncthreads();

    if (tid < CI * KK) {
        int o = tid / KK, k = tid % KK;
        float acc = 0.f;
#pragma unroll 8
        for (int c = 0; c < CI; c++) acc += kern[c * KK + k] * Win[o * CI + c];
        g_win[b * CI * KK + tid] = acc;
    }
    if (tid < CO) {
        float wo = 0.f, bi = 0.f;
#pragma unroll 4
        for (int i = 0; i < CI * KK; i++) {
            float kv = kern[i];
            wo += kv * Wout[tid * CI * KK + i];
            bi += kv * Wbias[tid * CI * KK + i];
        }
        g_wout[b * CO + tid] = wo;
        g_bias[b * CO + tid] = bi;
    }
}

// ---------------------------------------------------------------------------
// Kernel 3: z partials, c split 4 ways. Grid (8, 32, 4) = 1024 blocks x 256.
// Each thread: 4 consecutive l over 16 channels; halo via warp shuffle.
// ---------------------------------------------------------------------------
__global__ __launch_bounds__(ZTH) void z_kernel(const float* __restrict__ x) {
    const int b = blockIdx.y;
    const int g = blockIdx.z;
    const int lbase = blockIdx.x * ZTL;
    const int tid = threadIdx.x;
    const int lane = tid & 31;
    const int l0 = lbase + tid * 4;

    __shared__ float swin[CPG * KK];
    if (tid < CPG * KK)
        swin[tid] = g_win[b * CI * KK + g * CPG * KK + tid];
    __syncthreads();

    const float* xb = x + ((size_t)b * CI + g * CPG) * LL;

    float zx = 0.f, zy = 0.f, zz = 0.f, zw = 0.f;

#pragma unroll
    for (int c = 0; c < CPG; c++) {
        const float* xc = xb + (size_t)c * LL;
        float4 v = *reinterpret_cast<const float4*>(xc + l0);

        float lm = __shfl_up_sync(0xffffffffu, v.w, 1);
        if (lane == 0) lm = (l0 > 0) ? xc[l0 - 1] : 0.f;
        float rp = __shfl_down_sync(0xffffffffu, v.x, 1);
        if (lane == 31) rp = (l0 + 4 < LL) ? xc[l0 + 4] : 0.f;

        float w0 = swin[c * 3 + 0];
        float w1 = swin[c * 3 + 1];
        float w2 = swin[c * 3 + 2];

        zx = __fmaf_rn(w0, lm,  __fmaf_rn(w1, v.x, __fmaf_rn(w2, v.y, zx)));
        zy = __fmaf_rn(w0, v.x, __fmaf_rn(w1, v.y, __fmaf_rn(w2, v.z, zy)));
        zz = __fmaf_rn(w0, v.y, __fmaf_rn(w1, v.z, __fmaf_rn(w2, v.w, zz)));
        zw = __fmaf_rn(w0, v.z, __fmaf_rn(w1, v.w, __fmaf_rn(w2, rp,  zw)));
    }

    float4 r = make_float4(zx, zy, zz, zw);
    *reinterpret_cast<float4*>(&g_zp[g][b][l0]) = r;
}

// ---------------------------------------------------------------------------
// Kernel 4: y[b,o,l] = wout[b,o] * z[b,l] + bias[b,o]. Pure streaming stores.
// Grid (16, 32) = 512 blocks x 256 threads; 64 float4 stores per thread.
// ---------------------------------------------------------------------------
__global__ __launch_bounds__(YTH) void y_kernel(float* __restrict__ y) {
    const int b = blockIdx.y;
    const int lbase = blockIdx.x * YTL;
    const int tid = threadIdx.x;

    __shared__ float sz[YTL];
    __shared__ float swout[CO];
    __shared__ float sbias[CO];

    if (tid < CO) {
        swout[tid] = g_wout[b * CO + tid];
        sbias[tid] = g_bias[b * CO + tid];
    }
    // sum the 4 c-group partials (threads 0..127, one float4 each)
    if (tid < YTL / 4) {
        float4 a = reinterpret_cast<const float4*>(&g_zp[0][b][lbase])[tid];
        float4 c1 = reinterpret_cast<const float4*>(&g_zp[1][b][lbase])[tid];
        float4 c2 = reinterpret_cast<const float4*>(&g_zp[2][b][lbase])[tid];
        float4 c3 = reinterpret_cast<const float4*>(&g_zp[3][b][lbase])[tid];
        float4 s;
        s.x = (a.x + c1.x) + (c2.x + c3.x);
        s.y = (a.y + c1.y) + (c2.y + c3.y);
        s.z = (a.z + c1.z) + (c2.z + c3.z);
        s.w = (a.w + c1.w) + (c2.w + c3.w);
        reinterpret_cast<float4*>(sz)[tid] = s;
    }
    __syncthreads();

    float* yb = y + (size_t)b * CO * LL + lbase;
    const float4* sz4 = reinterpret_cast<const float4*>(sz);

#pragma unroll 4
    for (int i = tid; i < CO * (YTL / 4); i += YTH) {
        int o = i >> 7;          // / (YTL/4) = /128
        int l4 = i & 127;
        float4 zv = sz4[l4];
        float wo = swout[o], bi = sbias[o];
        float4 r;
        r.x = __fmaf_rn(wo, zv.x, bi);
        r.y = __fmaf_rn(wo, zv.y, bi);
        r.z = __fmaf_rn(wo, zv.z, bi);
        r.w = __fmaf_rn(wo, zv.w, bi);
        reinterpret_cast<float4*>(yb + (size_t)o * LL)[l4] = r;
    }
}

// ---------------------------------------------------------------------------
extern "C" void kernel_launch(void* const* d_in, const int* in_sizes, int n_in,
                              void* d_out, int out_size) {
    const float* x     = (const float*)d_in[0];
    const float* Wk    = (const float*)d_in[1];
    const float* Win   = (const float*)d_in[2];
    const float* Wout  = (const float*)d_in[3];
    const float* Wbias = (const float*)d_in[4];
    float* y = (float*)d_out;

    rowsum_kernel<<<B * CI, 256>>>(x);
    maker_kernel<<<B, 192>>>(x, Wk, Win, Wout, Wbias);
    dim3 zgrid(LL / ZTL, B, CG);
    z_kernel<<<zgrid, ZTH>>>(x);
    dim3 ygrid(LL / YTL, B);
    y_kernel<<<ygrid, YTH>>>(y);
}

// round 5
// speedup vs baseline: 1.2247x; 1.0158x over previous
#include <cuda_runtime.h>

#define B   32
#define CI  64
#define CO  128
#define KK  3
#define LL  8192

#define TL  256          // l per zy-block
#define NT  256          // threads per zy-block
#define CG  4            // in-block c-groups
#define CPG (CI / CG)    // 16 channels per group
#define GT  (NT / CG)    // 64 threads per group

__device__ float g_S[B * CI];
__device__ float g_win[B * CI * KK];
__device__ float g_wout[B * CO];
__device__ float g_bias[B * CO];

// ---------------------------------------------------------------------------
// Kernel 1: per-(b,c) row sums. 2048 blocks x 256 threads.
// ---------------------------------------------------------------------------
__global__ __launch_bounds__(256) void rowsum_kernel(const float* __restrict__ x) {
    const int row = blockIdx.x;
    const float4* p = reinterpret_cast<const float4*>(x + (size_t)row * LL);

    float4 v[8];
#pragma unroll
    for (int j = 0; j < 8; j++) v[j] = p[threadIdx.x + j * 256];

    float s = 0.f;
#pragma unroll
    for (int j = 0; j < 8; j++) s += (v[j].x + v[j].y) + (v[j].z + v[j].w);

#pragma unroll
    for (int off = 16; off > 0; off >>= 1)
        s += __shfl_xor_sync(0xffffffffu, s, off);

    __shared__ float wsum[8];
    if ((threadIdx.x & 31) == 0) wsum[threadIdx.x >> 5] = s;
    __syncthreads();
    if (threadIdx.x == 0) {
        float t = 0.f;
#pragma unroll
        for (int w = 0; w < 8; w++) t += wsum[w];
        g_S[row] = t;
    }
}

// ---------------------------------------------------------------------------
// Kernel 2: per-batch maker math. 32 blocks x 192 threads.
// ---------------------------------------------------------------------------
__global__ void maker_kernel(const float* __restrict__ x,
                             const float* __restrict__ Wk,
                             const float* __restrict__ Win,
                             const float* __restrict__ Wout,
                             const float* __restrict__ Wbias) {
    int b = blockIdx.x;
    int tid = threadIdx.x;
    __shared__ float kern[CI * KK];
    __shared__ float sS[CI], sx0[CI], sxl[CI];

    if (tid < CI) {
        sS[tid] = g_S[b * CI + tid];
        const float* xb = x + ((size_t)b * CI + tid) * LL;
        sx0[tid] = xb[0];
        sxl[tid] = xb[LL - 1];
    }
    __syncthreads();

    if (tid < CI * KK) {
        int c = tid / KK;
        float S = sS[c];
        float t0 = S - sxl[c];
        float t2 = S - sx0[c];
        kern[tid] = (Wk[tid * 3 + 0] * t0 + Wk[tid * 3 + 1] * S +
                     Wk[tid * 3 + 2] * t2) * (1.0f / LL);
    }
    __syncthreads();

    if (tid < CI * KK) {
        int o = tid / KK, k = tid % KK;
        float acc = 0.f;
#pragma unroll 8
        for (int c = 0; c < CI; c++) acc += kern[c * KK + k] * Win[o * CI + c];
        g_win[b * CI * KK + tid] = acc;
    }
    if (tid < CO) {
        float wo = 0.f, bi = 0.f;
#pragma unroll 4
        for (int i = 0; i < CI * KK; i++) {
            float kv = kern[i];
            wo += kv * Wout[tid * CI * KK + i];
            bi += kv * Wbias[tid * CI * KK + i];
        }
        g_wout[b * CO + tid] = wo;
        g_bias[b * CO + tid] = bi;
    }
}

// ---------------------------------------------------------------------------
// Kernel 3 (fused): z for TL=256 l-positions with 4-way in-block c-split,
// then streaming broadcast epilogue. Grid (32, 32) = 1024 blocks x 256 thr.
// ---------------------------------------------------------------------------
__global__ __launch_bounds__(NT) void zy_kernel(const float* __restrict__ x,
                                                float* __restrict__ y) {
    __shared__ float zp[CG][TL];
    __shared__ float sz[TL];
    __shared__ float swin[CI * KK];
    __shared__ float swout[CO];
    __shared__ float sbias[CO];

    const int b = blockIdx.y;
    const int lbase = blockIdx.x * TL;
    const int tid = threadIdx.x;
    const int lane = tid & 31;
    const int g = tid >> 6;         // c-group 0..3
    const int t = tid & (GT - 1);   // 0..63 within group
    const int l0 = lbase + t * 4;

    if (tid < CO) {
        swout[tid] = g_wout[b * CO + tid];
        sbias[tid] = g_bias[b * CO + tid];
    }
    if (tid < CI * KK) swin[tid] = g_win[b * CI * KK + tid];
    __syncthreads();

    // ---- z phase: 16 channels per group of 64 threads, 4 l per thread ----
    const float* xb = x + ((size_t)b * CI + g * CPG) * LL;
    float zx = 0.f, zy_ = 0.f, zz = 0.f, zw = 0.f;

#pragma unroll
    for (int c = 0; c < CPG; c++) {
        const float* xc = xb + (size_t)c * LL;
        float4 v = *reinterpret_cast<const float4*>(xc + l0);

        float lm = __shfl_up_sync(0xffffffffu, v.w, 1);
        if (lane == 0) lm = (l0 > 0) ? xc[l0 - 1] : 0.f;
        float rp = __shfl_down_sync(0xffffffffu, v.x, 1);
        if (lane == 31) rp = (l0 + 4 < LL) ? xc[l0 + 4] : 0.f;

        const float* w = swin + (g * CPG + c) * KK;
        float w0 = w[0], w1 = w[1], w2 = w[2];

        zx  = __fmaf_rn(w0, lm,  __fmaf_rn(w1, v.x, __fmaf_rn(w2, v.y, zx)));
        zy_ = __fmaf_rn(w0, v.x, __fmaf_rn(w1, v.y, __fmaf_rn(w2, v.z, zy_)));
        zz  = __fmaf_rn(w0, v.y, __fmaf_rn(w1, v.z, __fmaf_rn(w2, v.w, zz)));
        zw  = __fmaf_rn(w0, v.z, __fmaf_rn(w1, v.w, __fmaf_rn(w2, rp,  zw)));
    }
    *reinterpret_cast<float4*>(&zp[g][t * 4]) = make_float4(zx, zy_, zz, zw);
    __syncthreads();

    // combine 4 partials -> sz (64 threads, one float4 each)
    if (tid < TL / 4) {
        float4 a = reinterpret_cast<const float4*>(zp[0])[tid];
        float4 c1 = reinterpret_cast<const float4*>(zp[1])[tid];
        float4 c2 = reinterpret_cast<const float4*>(zp[2])[tid];
        float4 c3 = reinterpret_cast<const float4*>(zp[3])[tid];
        float4 s;
        s.x = (a.x + c1.x) + (c2.x + c3.x);
        s.y = (a.y + c1.y) + (c2.y + c3.y);
        s.z = (a.z + c1.z) + (c2.z + c3.z);
        s.w = (a.w + c1.w) + (c2.w + c3.w);
        reinterpret_cast<float4*>(sz)[tid] = s;
    }
    __syncthreads();

    // ---- y phase: 128 o x 64 float4, streaming stores (evict-first) ----
    float* yb = y + (size_t)b * CO * LL + lbase;
    const float4* sz4 = reinterpret_cast<const float4*>(sz);

#pragma unroll 8
    for (int i = tid; i < CO * (TL / 4); i += NT) {
        int o = i >> 6;          // / (TL/4) = /64
        int l4 = i & 63;
        float4 zv = sz4[l4];
        float wo = swout[o], bi = sbias[o];
        float4 r;
        r.x = __fmaf_rn(wo, zv.x, bi);
        r.y = __fmaf_rn(wo, zv.y, bi);
        r.z = __fmaf_rn(wo, zv.z, bi);
        r.w = __fmaf_rn(wo, zv.w, bi);
        __stcs(reinterpret_cast<float4*>(yb + (size_t)o * LL) + l4, r);
    }
}

// ---------------------------------------------------------------------------
extern "C" void kernel_launch(void* const* d_in, const int* in_sizes, int n_in,
                              void* d_out, int out_size) {
    const float* x     = (const float*)d_in[0];
    const float* Wk    = (const float*)d_in[1];
    const float* Win   = (const float*)d_in[2];
    const float* Wout  = (const float*)d_in[3];
    const float* Wbias = (const float*)d_in[4];
    float* y = (float*)d_out;

    rowsum_kernel<<<B * CI, 256>>>(x);
    maker_kernel<<<B, 192>>>(x, Wk, Win, Wout, Wbias);
    dim3 zygrid(LL / TL, B);
    zy_kernel<<<zygrid, NT>>>(x, y);
}

// round 6
// speedup vs baseline: 1.7964x; 1.4669x over previous
#include <cuda_runtime.h>

#define B   32
#define CI  64
#define CO  128
#define KK  3
#define LL  8192

#define TL  256          // l per zy-block
#define NT  256          // threads per zy-block
#define CG  4            // in-block c-groups
#define CPG (CI / CG)    // 16 channels per group
#define GT  (NT / CG)    // 64 threads per group

#define MPART 4          // maker o-partitions
#define OPP  (CO / MPART) // 32 o per maker block

__device__ float g_S[B * CI];
__device__ float g_win[B * CI * KK];
__device__ float g_wout[B * CO];
__device__ float g_bias[B * CO];

// ---------------------------------------------------------------------------
// Kernel 1: per-(b,c) row sums. 2048 blocks x 256 threads.
// ---------------------------------------------------------------------------
__global__ __launch_bounds__(256) void rowsum_kernel(const float* __restrict__ x) {
    const int row = blockIdx.x;
    const float4* p = reinterpret_cast<const float4*>(x + (size_t)row * LL);

    float4 v[8];
#pragma unroll
    for (int j = 0; j < 8; j++) v[j] = p[threadIdx.x + j * 256];

    float s = 0.f;
#pragma unroll
    for (int j = 0; j < 8; j++) s += (v[j].x + v[j].y) + (v[j].z + v[j].w);

#pragma unroll
    for (int off = 16; off > 0; off >>= 1)
        s += __shfl_xor_sync(0xffffffffu, s, off);

    __shared__ float wsum[8];
    if ((threadIdx.x & 31) == 0) wsum[threadIdx.x >> 5] = s;
    __syncthreads();
    if (threadIdx.x == 0) {
        float t = 0.f;
#pragma unroll
        for (int w = 0; w < 8; w++) t += wsum[w];
        g_S[row] = t;
    }
}

// ---------------------------------------------------------------------------
// Kernel 2: maker. Grid (4, 32) x 256 threads.
// kern computed redundantly per block (tiny); w_in by part 0 only;
// w_out/bias via warp-per-o coalesced lane-parallel dot + shuffle reduce.
// ---------------------------------------------------------------------------
__global__ __launch_bounds__(256) void maker_kernel(const float* __restrict__ x,
                             const float* __restrict__ Wk,
                             const float* __restrict__ Win,
                             const float* __restrict__ Wout,
                             const float* __restrict__ Wbias) {
    const int b = blockIdx.y;
    const int part = blockIdx.x;
    const int tid = threadIdx.x;
    const int wid = tid >> 5;
    const int lane = tid & 31;

    __shared__ float kern[CI * KK];
    __shared__ float sS[CI], sx0[CI], sxl[CI];

    if (tid < CI) {
        sS[tid] = g_S[b * CI + tid];
        const float* xb = x + ((size_t)b * CI + tid) * LL;
        sx0[tid] = xb[0];
        sxl[tid] = xb[LL - 1];
    }
    __syncthreads();

    if (tid < CI * KK) {
        int c = tid / KK;
        float S = sS[c];
        float t0 = S - sxl[c];
        float t2 = S - sx0[c];
        kern[tid] = (Wk[tid * 3 + 0] * t0 + Wk[tid * 3 + 1] * S +
                     Wk[tid * 3 + 2] * t2) * (1.0f / LL);
    }
    __syncthreads();

    if (part == 0 && tid < CI * KK) {
        int o = tid / KK, k = tid % KK;
        float acc = 0.f;
#pragma unroll 8
        for (int c = 0; c < CI; c++) acc += kern[c * KK + k] * Win[o * CI + c];
        g_win[b * CI * KK + tid] = acc;
    }

    // w_out/bias: 8 warps, each handles 4 of this block's 32 o's.
#pragma unroll
    for (int j = 0; j < OPP / 8; j++) {
        int o = part * OPP + wid * (OPP / 8) + j;
        const float* wo_row = Wout  + (size_t)o * (CI * KK);
        const float* wb_row = Wbias + (size_t)o * (CI * KK);
        float aco = 0.f, acb = 0.f;
#pragma unroll
        for (int i = lane; i < CI * KK; i += 32) {
            float kv = kern[i];
            aco = __fmaf_rn(kv, wo_row[i], aco);
            acb = __fmaf_rn(kv, wb_row[i], acb);
        }
#pragma unroll
        for (int off = 16; off > 0; off >>= 1) {
            aco += __shfl_xor_sync(0xffffffffu, aco, off);
            acb += __shfl_xor_sync(0xffffffffu, acb, off);
        }
        if (lane == 0) {
            g_wout[b * CO + o] = aco;
            g_bias[b * CO + o] = acb;
        }
    }
}

// ---------------------------------------------------------------------------
// Kernel 3 (fused): z with 4-way in-block c-split (NO shuffles — halo via
// direct scalar loads that hit L1), then streaming broadcast epilogue.
// Grid (32, 32) = 1024 blocks x 256 threads.
// ---------------------------------------------------------------------------
__global__ __launch_bounds__(NT) void zy_kernel(const float* __restrict__ x,
                                                float* __restrict__ y) {
    __shared__ float zp[CG][TL];
    __shared__ float sz[TL];
    __shared__ float swin[CI * KK];
    __shared__ float swout[CO];
    __shared__ float sbias[CO];

    const int b = blockIdx.y;
    const int lbase = blockIdx.x * TL;
    const int tid = threadIdx.x;
    const int g = tid >> 6;         // c-group 0..3
    const int t = tid & (GT - 1);   // 0..63 within group
    const int l0 = lbase + t * 4;

    if (tid < CO) {
        swout[tid] = g_wout[b * CO + tid];
        sbias[tid] = g_bias[b * CO + tid];
    }
    if (tid < CI * KK) swin[tid] = g_win[b * CI * KK + tid];
    __syncthreads();

    // ---- z phase ----
    const float* xb = x + ((size_t)b * CI + g * CPG) * LL;
    float zx = 0.f, zy_ = 0.f, zz = 0.f, zw = 0.f;

#pragma unroll 4
    for (int c = 0; c < CPG; c++) {
        const float* xc = xb + (size_t)c * LL;
        float4 v = *reinterpret_cast<const float4*>(xc + l0);
        float lm = (l0 > 0)      ? xc[l0 - 1] : 0.f;   // L1 hit (neighbor's line)
        float rp = (l0 + 4 < LL) ? xc[l0 + 4] : 0.f;   // L1 hit

        const float* w = swin + (g * CPG + c) * KK;
        float w0 = w[0], w1 = w[1], w2 = w[2];

        zx  = __fmaf_rn(w0, lm,  __fmaf_rn(w1, v.x, __fmaf_rn(w2, v.y, zx)));
        zy_ = __fmaf_rn(w0, v.x, __fmaf_rn(w1, v.y, __fmaf_rn(w2, v.z, zy_)));
        zz  = __fmaf_rn(w0, v.y, __fmaf_rn(w1, v.z, __fmaf_rn(w2, v.w, zz)));
        zw  = __fmaf_rn(w0, v.z, __fmaf_rn(w1, v.w, __fmaf_rn(w2, rp,  zw)));
    }
    *reinterpret_cast<float4*>(&zp[g][t * 4]) = make_float4(zx, zy_, zz, zw);
    __syncthreads();

    if (tid < TL / 4) {
        float4 a  = reinterpret_cast<const float4*>(zp[0])[tid];
        float4 c1 = reinterpret_cast<const float4*>(zp[1])[tid];
        float4 c2 = reinterpret_cast<const float4*>(zp[2])[tid];
        float4 c3 = reinterpret_cast<const float4*>(zp[3])[tid];
        float4 s;
        s.x = (a.x + c1.x) + (c2.x + c3.x);
        s.y = (a.y + c1.y) + (c2.y + c3.y);
        s.z = (a.z + c1.z) + (c2.z + c3.z);
        s.w = (a.w + c1.w) + (c2.w + c3.w);
        reinterpret_cast<float4*>(sz)[tid] = s;
    }
    __syncthreads();

    // ---- y phase: streaming stores ----
    float* yb = y + (size_t)b * CO * LL + lbase;
    const float4* sz4 = reinterpret_cast<const float4*>(sz);

#pragma unroll 8
    for (int i = tid; i < CO * (TL / 4); i += NT) {
        int o = i >> 6;
        int l4 = i & 63;
        float4 zv = sz4[l4];
        float wo = swout[o], bi = sbias[o];
        float4 r;
        r.x = __fmaf_rn(wo, zv.x, bi);
        r.y = __fmaf_rn(wo, zv.y, bi);
        r.z = __fmaf_rn(wo, zv.z, bi);
        r.w = __fmaf_rn(wo, zv.w, bi);
        __stcs(reinterpret_cast<float4*>(yb + (size_t)o * LL) + l4, r);
    }
}

// ---------------------------------------------------------------------------
extern "C" void kernel_launch(void* const* d_in, const int* in_sizes, int n_in,
                              void* d_out, int out_size) {
    const float* x     = (const float*)d_in[0];
    const float* Wk    = (const float*)d_in[1];
    const float* Win   = (const float*)d_in[2];
    const float* Wout  = (const float*)d_in[3];
    const float* Wbias = (const float*)d_in[4];
    float* y = (float*)d_out;

    rowsum_kernel<<<B * CI, 256>>>(x);
    dim3 mgrid(MPART, B);
    maker_kernel<<<mgrid, 256>>>(x, Wk, Win, Wout, Wbias);
    dim3 zygrid(LL / TL, B);
    zy_kernel<<<zygrid, NT>>>(x, y);
}

// round 8
// speedup vs baseline: 1.9294x; 1.0740x over previous
#include <cuda_runtime.h>

#define B   32
#define CI  64
#define CO  128
#define KK  3
#define LL  8192

#define ZTL 256          // l per z-block
#define ZNT 256          // threads per z-block
#define CG  4            // in-block c-groups
#define CPG (CI / CG)    // 16 channels per group
#define GT  (ZNT / CG)   // 64 threads per group

#define YTL 128          // l per y-block
#define YNT 256

#define MPART 4
#define OPP  (CO / MPART)

__device__ float g_S[B * CI];
__device__ float g_win[B * CI * KK];
__device__ float g_wout[B * CO];
__device__ float g_bias[B * CO];
__device__ float g_z[B][LL];       // 1MB

// ---------------------------------------------------------------------------
// Kernel 1: per-(b,c) row sums. 2048 blocks x 128 threads, 16 float4 each.
// ---------------------------------------------------------------------------
__global__ __launch_bounds__(128) void rowsum_kernel(const float* __restrict__ x) {
    const int row = blockIdx.x;
    const float4* p = reinterpret_cast<const float4*>(x + (size_t)row * LL);

    float4 v[16];
#pragma unroll
    for (int j = 0; j < 16; j++) v[j] = p[threadIdx.x + j * 128];

    float s = 0.f;
#pragma unroll
    for (int j = 0; j < 16; j++) s += (v[j].x + v[j].y) + (v[j].z + v[j].w);

#pragma unroll
    for (int off = 16; off > 0; off >>= 1)
        s += __shfl_xor_sync(0xffffffffu, s, off);

    __shared__ float wsum[4];
    if ((threadIdx.x & 31) == 0) wsum[threadIdx.x >> 5] = s;
    __syncthreads();
    if (threadIdx.x == 0)
        g_S[row] = (wsum[0] + wsum[1]) + (wsum[2] + wsum[3]);
}

// ---------------------------------------------------------------------------
// Kernel 2: maker. Grid (4, 32) x 256 threads.
// kern redundant per block; w_in by part 0; w_out/bias warp-per-o coalesced.
// ---------------------------------------------------------------------------
__global__ __launch_bounds__(256) void maker_kernel(const float* __restrict__ x,
                             const float* __restrict__ Wk,
                             const float* __restrict__ Win,
                             const float* __restrict__ Wout,
                             const float* __restrict__ Wbias) {
    const int b = blockIdx.y;
    const int part = blockIdx.x;
    const int tid = threadIdx.x;
    const int wid = tid >> 5;
    const int lane = tid & 31;

    __shared__ float kern[CI * KK];
    __shared__ float sS[CI], sx0[CI], sxl[CI];

    if (tid < CI) {
        sS[tid] = g_S[b * CI + tid];
        const float* xb = x + ((size_t)b * CI + tid) * LL;
        sx0[tid] = xb[0];
        sxl[tid] = xb[LL - 1];
    }
    __syncthreads();

    if (tid < CI * KK) {
        int c = tid / KK;
        float S = sS[c];
        float t0 = S - sxl[c];
        float t2 = S - sx0[c];
        kern[tid] = (Wk[tid * 3 + 0] * t0 + Wk[tid * 3 + 1] * S +
                     Wk[tid * 3 + 2] * t2) * (1.0f / LL);
    }
    __syncthreads();

    if (part == 0 && tid < CI * KK) {
        int o = tid / KK, k = tid % KK;
        float acc = 0.f;
#pragma unroll 8
        for (int c = 0; c < CI; c++) acc += kern[c * KK + k] * Win[o * CI + c];
        g_win[b * CI * KK + tid] = acc;
    }

#pragma unroll
    for (int j = 0; j < OPP / 8; j++) {
        int o = part * OPP + wid * (OPP / 8) + j;
        const float* wo_row = Wout  + (size_t)o * (CI * KK);
        const float* wb_row = Wbias + (size_t)o * (CI * KK);
        float aco = 0.f, acb = 0.f;
#pragma unroll
        for (int i = lane; i < CI * KK; i += 32) {
            float kv = kern[i];
            aco = __fmaf_rn(kv, wo_row[i], aco);
            acb = __fmaf_rn(kv, wb_row[i], acb);
        }
#pragma unroll
        for (int off = 16; off > 0; off >>= 1) {
            aco += __shfl_xor_sync(0xffffffffu, aco, off);
            acb += __shfl_xor_sync(0xffffffffu, acb, off);
        }
        if (lane == 0) {
            g_wout[b * CO + o] = aco;
            g_bias[b * CO + o] = acb;
        }
    }
}

// ---------------------------------------------------------------------------
// Kernel 3: z with 4-way in-block c-split (no shuffles). Grid (32,32) x 256.
// ---------------------------------------------------------------------------
__global__ __launch_bounds__(ZNT) void z_kernel(const float* __restrict__ x) {
    __shared__ float zp[CG][ZTL];
    __shared__ float swin[CI * KK];

    const int b = blockIdx.y;
    const int lbase = blockIdx.x * ZTL;
    const int tid = threadIdx.x;
    const int g = tid >> 6;
    const int t = tid & (GT - 1);
    const int l0 = lbase + t * 4;

    if (tid < CI * KK) swin[tid] = g_win[b * CI * KK + tid];
    __syncthreads();

    const float* xb = x + ((size_t)b * CI + g * CPG) * LL;
    float zx = 0.f, zy_ = 0.f, zz = 0.f, zw = 0.f;

#pragma unroll 4
    for (int c = 0; c < CPG; c++) {
        const float* xc = xb + (size_t)c * LL;
        float4 v = *reinterpret_cast<const float4*>(xc + l0);
        float lm = (l0 > 0)      ? xc[l0 - 1] : 0.f;   // L1 hit
        float rp = (l0 + 4 < LL) ? xc[l0 + 4] : 0.f;   // L1 hit

        const float* w = swin + (g * CPG + c) * KK;
        float w0 = w[0], w1 = w[1], w2 = w[2];

        zx  = __fmaf_rn(w0, lm,  __fmaf_rn(w1, v.x, __fmaf_rn(w2, v.y, zx)));
        zy_ = __fmaf_rn(w0, v.x, __fmaf_rn(w1, v.y, __fmaf_rn(w2, v.z, zy_)));
        zz  = __fmaf_rn(w0, v.y, __fmaf_rn(w1, v.z, __fmaf_rn(w2, v.w, zz)));
        zw  = __fmaf_rn(w0, v.z, __fmaf_rn(w1, v.w, __fmaf_rn(w2, rp,  zw)));
    }
    *reinterpret_cast<float4*>(&zp[g][t * 4]) = make_float4(zx, zy_, zz, zw);
    __syncthreads();

    if (tid < ZTL / 4) {
        float4 a  = reinterpret_cast<const float4*>(zp[0])[tid];
        float4 c1 = reinterpret_cast<const float4*>(zp[1])[tid];
        float4 c2 = reinterpret_cast<const float4*>(zp[2])[tid];
        float4 c3 = reinterpret_cast<const float4*>(zp[3])[tid];
        float4 s;
        s.x = (a.x + c1.x) + (c2.x + c3.x);
        s.y = (a.y + c1.y) + (c2.y + c3.y);
        s.z = (a.z + c1.z) + (c2.z + c3.z);
        s.w = (a.w + c1.w) + (c2.w + c3.w);
        reinterpret_cast<float4*>(&g_z[b][lbase])[tid] = s;
    }
}

// ---------------------------------------------------------------------------
// Kernel 4: y = wout*z + bias. Grid (64, 32) = 2048 blocks x 256 threads.
// Each block: 128 l x 128 o; 16 float4 streaming stores per thread.
// ---------------------------------------------------------------------------
__global__ __launch_bounds__(YNT) void y_kernel(float* __restrict__ y) {
    __shared__ float sz[YTL];
    __shared__ float swout[CO];
    __shared__ float sbias[CO];

    const int b = blockIdx.y;
    const int lbase = blockIdx.x * YTL;
    const int tid = threadIdx.x;

    if (tid < CO) {
        swout[tid] = g_wout[b * CO + tid];
        sbias[tid] = g_bias[b * CO + tid];
    }
    if (tid < YTL / 4)
        reinterpret_cast<float4*>(sz)[tid] =
            reinterpret_cast<const float4*>(&g_z[b][lbase])[tid];
    __syncthreads();

    float* yb = y + (size_t)b * CO * LL + lbase;
    const float4* sz4 = reinterpret_cast<const float4*>(sz);

#pragma unroll 16
    for (int i = tid; i < CO * (YTL / 4); i += YNT) {
        int o = i >> 5;          // / (YTL/4) = /32
        int l4 = i & 31;
        float4 zv = sz4[l4];
        float wo = swout[o], bi = sbias[o];
        float4 r;
        r.x = __fmaf_rn(wo, zv.x, bi);
        r.y = __fmaf_rn(wo, zv.y, bi);
        r.z = __fmaf_rn(wo, zv.z, bi);
        r.w = __fmaf_rn(wo, zv.w, bi);
        __stcs(reinterpret_cast<float4*>(yb + (size_t)o * LL) + l4, r);
    }
}

// ---------------------------------------------------------------------------
extern "C" void kernel_launch(void* const* d_in, const int* in_sizes, int n_in,
                              void* d_out, int out_size) {
    const float* x     = (const float*)d_in[0];
    const float* Wk    = (const float*)d_in[1];
    const float* Win   = (const float*)d_in[2];
    const float* Wout  = (const float*)d_in[3];
    const float* Wbias = (const float*)d_in[4];
    float* y = (float*)d_out;

    rowsum_kernel<<<B * CI, 128>>>(x);
    dim3 mgrid(MPART, B);
    maker_kernel<<<mgrid, 256>>>(x, Wk, Win, Wout, Wbias);
    dim3 zgrid(LL / ZTL, B);
    z_kernel<<<zgrid, ZNT>>>(x);
    dim3 ygrid(LL / YTL, B);
    y_kernel<<<ygrid, YNT>>>(y);
}

// round 9
// speedup vs baseline: 1.9928x; 1.0329x over previous
#include <cuda_runtime.h>

#define B   32
#define CI  64
#define CO  128
#define KK  3
#define LL  8192

#define ZTL 256
#define ZNT 256
#define CG  4
#define CPG (CI / CG)    // 16
#define GT  (ZNT / CG)   // 64

#define YTL 128
#define YNT 256

#define MPART 4
#define OPP  (CO / MPART)

__device__ float g_S[B * CI];
__device__ float g_win[B * CI * KK];
__device__ float g_wout[B * CO];
__device__ float g_bias[B * CO];
__device__ float g_z[B][LL];

// ---------------------------------------------------------------------------
// Kernel 1: per-(b,c) row sums. 2048 blocks x 128 threads, 16 float4 each.
// ---------------------------------------------------------------------------
__global__ __launch_bounds__(128) void rowsum_kernel(const float* __restrict__ x) {
    const int row = blockIdx.x;
    const float4* p = reinterpret_cast<const float4*>(x + (size_t)row * LL);

    float4 v[16];
#pragma unroll
    for (int j = 0; j < 16; j++) v[j] = p[threadIdx.x + j * 128];

    float s = 0.f;
#pragma unroll
    for (int j = 0; j < 16; j++) s += (v[j].x + v[j].y) + (v[j].z + v[j].w);

#pragma unroll
    for (int off = 16; off > 0; off >>= 1)
        s += __shfl_xor_sync(0xffffffffu, s, off);

    __shared__ float wsum[4];
    if ((threadIdx.x & 31) == 0) wsum[threadIdx.x >> 5] = s;
    __syncthreads();
    if (threadIdx.x == 0)
        g_S[row] = (wsum[0] + wsum[1]) + (wsum[2] + wsum[3]);
}

// ---------------------------------------------------------------------------
// Kernel 2: maker. Grid (4, 32) x 256 threads.
// ---------------------------------------------------------------------------
__global__ __launch_bounds__(256) void maker_kernel(const float* __restrict__ x,
                             const float* __restrict__ Wk,
                             const float* __restrict__ Win,
                             const float* __restrict__ Wout,
                             const float* __restrict__ Wbias) {
    const int b = blockIdx.y;
    const int part = blockIdx.x;
    const int tid = threadIdx.x;
    const int wid = tid >> 5;
    const int lane = tid & 31;

    __shared__ float kern[CI * KK];
    __shared__ float sS[CI], sx0[CI], sxl[CI];

    if (tid < CI) {
        sS[tid] = g_S[b * CI + tid];
        const float* xb = x + ((size_t)b * CI + tid) * LL;
        sx0[tid] = xb[0];
        sxl[tid] = xb[LL - 1];
    }
    __syncthreads();

    if (tid < CI * KK) {
        int c = tid / KK;
        float S = sS[c];
        float t0 = S - sxl[c];
        float t2 = S - sx0[c];
        kern[tid] = (Wk[tid * 3 + 0] * t0 + Wk[tid * 3 + 1] * S +
                     Wk[tid * 3 + 2] * t2) * (1.0f / LL);
    }
    __syncthreads();

    if (part == 0 && tid < CI * KK) {
        int o = tid / KK, k = tid % KK;
        float acc = 0.f;
#pragma unroll 8
        for (int c = 0; c < CI; c++) acc += kern[c * KK + k] * Win[o * CI + c];
        g_win[b * CI * KK + tid] = acc;
    }

#pragma unroll
    for (int j = 0; j < OPP / 8; j++) {
        int o = part * OPP + wid * (OPP / 8) + j;
        const float* wo_row = Wout  + (size_t)o * (CI * KK);
        const float* wb_row = Wbias + (size_t)o * (CI * KK);
        float aco = 0.f, acb = 0.f;
#pragma unroll
        for (int i = lane; i < CI * KK; i += 32) {
            float kv = kern[i];
            aco = __fmaf_rn(kv, wo_row[i], aco);
            acb = __fmaf_rn(kv, wb_row[i], acb);
        }
#pragma unroll
        for (int off = 16; off > 0; off >>= 1) {
            aco += __shfl_xor_sync(0xffffffffu, aco, off);
            acb += __shfl_xor_sync(0xffffffffu, acb, off);
        }
        if (lane == 0) {
            g_wout[b * CO + o] = aco;
            g_bias[b * CO + o] = acb;
        }
    }
}

// ---------------------------------------------------------------------------
// Kernel 3: z, scatter formulation. Grid (32,32) x 256 threads.
// Each thread: ONE float4 per channel, no halo loads (except group-edge
// threads: 1 predicated scalar). Contributions to z[l0-1..l0+4] kept in
// 6 registers; cross-thread overlap resolved via smem edge arrays.
// ---------------------------------------------------------------------------
__global__ __launch_bounds__(ZNT) void z_kernel(const float* __restrict__ x) {
    __shared__ float zp[CG][ZTL];        // interior a0..a3 per thread
    __shared__ float edgeL[CG][GT];      // contribution to z[l0-1]
    __shared__ float edgeR[CG][GT];      // contribution to z[l0+4]
    __shared__ float swin[CI * KK];

    const int b = blockIdx.y;
    const int lbase = blockIdx.x * ZTL;
    const int tid = threadIdx.x;
    const int g = tid >> 6;
    const int t = tid & (GT - 1);
    const int l0 = lbase + t * 4;

    if (tid < CI * KK) swin[tid] = g_win[b * CI * KK + tid];
    __syncthreads();

    const float* xb = x + ((size_t)b * CI + g * CPG) * LL;
    float aL = 0.f, a0 = 0.f, a1 = 0.f, a2 = 0.f, a3 = 0.f, aR = 0.f;

#pragma unroll 4
    for (int c = 0; c < CPG; c++) {
        const float* xc = xb + (size_t)c * LL;
        float4 v = *reinterpret_cast<const float4*>(xc + l0);

        const float* w = swin + (g * CPG + c) * KK;
        float w0 = w[0], w1 = w[1], w2 = w[2];

        aL = __fmaf_rn(w2, v.x, aL);
        a0 = __fmaf_rn(w1, v.x, __fmaf_rn(w2, v.y, a0));
        a1 = __fmaf_rn(w0, v.x, __fmaf_rn(w1, v.y, __fmaf_rn(w2, v.z, a1)));
        a2 = __fmaf_rn(w0, v.y, __fmaf_rn(w1, v.z, __fmaf_rn(w2, v.w, a2)));
        a3 = __fmaf_rn(w0, v.z, __fmaf_rn(w1, v.w, a3));
        aR = __fmaf_rn(w0, v.w, aR);

        // block-boundary terms (only group-edge threads; L1 hits)
        if (t == 0 && l0 > 0)
            a0 = __fmaf_rn(w0, xc[l0 - 1], a0);
        if (t == GT - 1 && l0 + 4 < LL)
            a3 = __fmaf_rn(w2, xc[l0 + 4], a3);
    }

    *reinterpret_cast<float4*>(&zp[g][t * 4]) = make_float4(a0, a1, a2, a3);
    edgeL[g][t] = aL;
    edgeR[g][t] = aR;
    __syncthreads();

    // combine 4 groups + neighbor edges (64 threads, one float4 each)
    if (tid < ZTL / 4) {
        int j = tid;
        float4 s = make_float4(0.f, 0.f, 0.f, 0.f);
#pragma unroll
        for (int gg = 0; gg < CG; gg++) {
            float4 a = reinterpret_cast<const float4*>(zp[gg])[j];
            s.x += a.x; s.y += a.y; s.z += a.z; s.w += a.w;
            if (j > 0)      s.x += edgeR[gg][j - 1];
            if (j < GT - 1) s.w += edgeL[gg][j + 1];
        }
        reinterpret_cast<float4*>(&g_z[b][lbase])[j] = s;
    }
}

// ---------------------------------------------------------------------------
// Kernel 4: y = wout*z + bias. Grid (64, 32) x 256 threads.
// zv hoisted (constant per thread); pointer-increment o-loop.
// ---------------------------------------------------------------------------
__global__ __launch_bounds__(YNT) void y_kernel(float* __restrict__ y) {
    __shared__ float sz[YTL];
    __shared__ float swout[CO];
    __shared__ float sbias[CO];

    const int b = blockIdx.y;
    const int lbase = blockIdx.x * YTL;
    const int tid = threadIdx.x;

    if (tid < CO) {
        swout[tid] = g_wout[b * CO + tid];
        sbias[tid] = g_bias[b * CO + tid];
    }
    if (tid < YTL / 4)
        reinterpret_cast<float4*>(sz)[tid] =
            reinterpret_cast<const float4*>(&g_z[b][lbase])[tid];
    __syncthreads();

    const int l4 = tid & 31;       // float4 index within tile (constant)
    const int o0 = tid >> 5;       // first o (0..7)
    const float4 zv = reinterpret_cast<const float4*>(sz)[l4];

    float4* p = reinterpret_cast<float4*>(
        y + (size_t)b * CO * LL + (size_t)o0 * LL + lbase) + l4;

#pragma unroll
    for (int k = 0; k < CO / 8; k++) {
        int o = o0 + k * 8;
        float wo = swout[o], bi = sbias[o];
        float4 r;
        r.x = __fmaf_rn(wo, zv.x, bi);
        r.y = __fmaf_rn(wo, zv.y, bi);
        r.z = __fmaf_rn(wo, zv.z, bi);
        r.w = __fmaf_rn(wo, zv.w, bi);
        __stcs(p, r);
        p += 2 * LL;               // 8 rows * LL floats / 4 per float4
    }
}

// ---------------------------------------------------------------------------
extern "C" void kernel_launch(void* const* d_in, const int* in_sizes, int n_in,
                              void* d_out, int out_size) {
    const float* x     = (const float*)d_in[0];
    const float* Wk    = (const float*)d_in[1];
    const float* Win   = (const float*)d_in[2];
    const float* Wout  = (const float*)d_in[3];
    const float* Wbias = (const float*)d_in[4];
    float* y = (float*)d_out;

    rowsum_kernel<<<B * CI, 128>>>(x);
    dim3 mgrid(MPART, B);
    maker_kernel<<<mgrid, 256>>>(x, Wk, Win, Wout, Wbias);
    dim3 zgrid(LL / ZTL, B);
    z_kernel<<<zgrid, ZNT>>>(x);
    dim3 ygrid(LL / YTL, B);
    y_kernel<<<ygrid, YNT>>>(y);
}